// round 14
// baseline (speedup 1.0000x reference)
#include <cuda_runtime.h>
#include <cuda_fp16.h>
#include <math.h>

#define NF      1044
#define VOCAB   9396
#define NCH     33                 // 33 chunks x 32 fields (128 k) = 4224 >= 4176
#define KROW    4224
#define ASTRIDE 272                // A row: 128 halves + 8 pad
#define ABUF    (128*ASTRIDE)      // 34816
#define B_OFF   (2*ABUF)           // 69632
#define BBUF    (128*80)           // 10240: B chunk [128 k][40 halves]
#define E_OFF   (B_OFF+2*BBUF)     // 90112
#define WL_OFF  (E_OFF+VOCAB*8)    // 165280
#define PRM_OFF (WL_OFF+VOCAB*4)   // 202864
#define LIN_OFF (PRM_OFF+4616)     // 207480
#define MBAR_OFF 207992
#define SMEM_SZ  208032
#define BN_INV 0.9999950000374997f

__device__ __align__(16) unsigned char g_e16[VOCAB*8];   // fp16 emb [VOCAB][4]
__device__ __align__(16) unsigned char g_Bw[KROW*80];    // fp16 w1  [KROW][40]

__global__ void build_e16(const float* __restrict__ emb) {
    int g = blockIdx.x*256 + threadIdx.x;
    if (g >= VOCAB) return;
    __half h[4];
    #pragma unroll
    for (int d = 0; d < 4; d++) h[d] = __float2half_rn(emb[g*4+d]);
    *(uint2*)(g_e16 + g*8) = *(uint2*)h;
}
__global__ void build_Bw(const float* __restrict__ w1) {
    int t = blockIdx.x*256 + threadIdx.x;
    if (t >= KROW*20) return;
    int np = t % 20, kk = t / 20, n = np*2;
    float v0 = 0.f, v1 = 0.f;
    if (kk < 4176 && n < 32) { v0 = w1[kk*32+n]; v1 = w1[kk*32+n+1]; }
    *(__half2*)(g_Bw + kk*80 + n*2) = __floats2half2_rn(v0, v1);
}

__device__ __forceinline__ void mbar_init(unsigned m, unsigned c) {
    asm volatile("mbarrier.init.shared.b64 [%0], %1;" :: "r"(m), "r"(c) : "memory");
}
__device__ __forceinline__ void mbar_tx(unsigned m, unsigned b) {
    asm volatile("mbarrier.arrive.expect_tx.shared.b64 _, [%0], %1;"
                 :: "r"(m), "r"(b) : "memory");
}
__device__ __forceinline__ void bulk_g2s(unsigned d, const void* s,
                                         unsigned b, unsigned m) {
    asm volatile("cp.async.bulk.shared::cta.global.mbarrier::complete_tx::bytes "
                 "[%0], [%1], %2, [%3];" :: "r"(d), "l"(s), "r"(b), "r"(m) : "memory");
}
__device__ __forceinline__ void mbar_wait(unsigned m, unsigned p) {
    asm volatile(
        "{\n\t.reg .pred P;\nWL%=:\n\t"
        "mbarrier.try_wait.parity.acquire.cta.shared::cta.b64 P, [%0], %1, 0x989680;\n\t"
        "@!P bra WL%=;\n\t}" :: "r"(m), "r"(p) : "memory");
}
__device__ __forceinline__ int bucket(float x) {
    return (x > 5.0f) ? 8 : (int)(x + 2.0f);
}

#define MMA4(C, B0, B1) asm volatile( \
    "mma.sync.aligned.m16n8k16.row.col.f32.f16.f16.f32 " \
    "{%0,%1,%2,%3},{%4,%5,%6,%7},{%8,%9},{%0,%1,%2,%3};" \
    : "+f"((C)[0]), "+f"((C)[1]), "+f"((C)[2]), "+f"((C)[3]) \
    : "r"(a0), "r"(a1), "r"(a2), "r"(a3), "r"(B0), "r"(B1))

__global__ void __launch_bounds__(512, 1)
fused_mma(const float* __restrict__ state, const float* __restrict__ w_lin,
          const float* __restrict__ b1,  const float* __restrict__ g1,
          const float* __restrict__ be1,
          const float* __restrict__ w2,  const float* __restrict__ b2,
          const float* __restrict__ g2,  const float* __restrict__ be2,
          const float* __restrict__ w3,  const float* __restrict__ b3,
          const float* __restrict__ b_lin, float* __restrict__ out) {
    extern __shared__ char smem[];
    const int tid = threadIdx.x, lane = tid & 31, w = tid >> 5;
    const int mt = w >> 1, kh = w & 1;
    const int s0 = blockIdx.x * 128;
    const unsigned su = (unsigned)__cvta_generic_to_shared(smem);
    const unsigned mbE = su+MBAR_OFF, mbB0 = su+MBAR_OFF+8, mbB1 = su+MBAR_OFF+16;
    float* prm = (float*)(smem + PRM_OFF);

    if (tid == 0) { mbar_init(mbE,1); mbar_init(mbB0,1); mbar_init(mbB1,1); }
    __syncthreads();
    if (tid == 0) {
        mbar_tx(mbE, VOCAB*8 + VOCAB*4);
        bulk_g2s(su+E_OFF,  g_e16, VOCAB*8, mbE);
        bulk_g2s(su+WL_OFF, w_lin, VOCAB*4, mbE);
        mbar_tx(mbB0, BBUF); bulk_g2s(su+B_OFF,      g_Bw,      BBUF, mbB0);
        mbar_tx(mbB1, BBUF); bulk_g2s(su+B_OFF+BBUF, g_Bw+BBUF, BBUF, mbB1);
    }
    // chunk-0 state burst: warp = 8 samples, lane = field (coalesced)
    float sv[8];
    #pragma unroll
    for (int j = 0; j < 8; j++)
        sv[j] = state[(size_t)(s0 + w*8 + j)*NF + lane];
    for (int i = tid; i < 1154; i += 512) {
        float v;
        if (i < 1024)      v = w2[i];
        else if (i < 1056) v = b2[i-1024];
        else if (i < 1088) v = g2[i-1056];
        else if (i < 1120) v = be2[i-1088];
        else if (i < 1152) v = w3[i-1120];
        else if (i == 1152) v = b3[0];
        else               v = b_lin[0];
        prm[i] = v;
    }
    float linr[8];
    #pragma unroll
    for (int j = 0; j < 8; j++) linr[j] = 0.f;

    mbar_wait(mbE, 0);
    #pragma unroll
    for (int j = 0; j < 8; j++) {            // consume chunk 0 -> A buf 0
        int gidx = lane*9 + bucket(sv[j]);
        linr[j] += *(const float*)(smem + WL_OFF + gidx*4);
        *(uint2*)(smem + (w*8+j)*ASTRIDE + lane*8) =
            *(const uint2*)(smem + E_OFF + gidx*8);
    }
    __syncthreads();

    float acc[16];
    #pragma unroll
    for (int i = 0; i < 16; i++) acc[i] = 0.f;
    const unsigned arow = (unsigned)(lane & 15);
    const unsigned hi16 = (unsigned)(16*(lane >> 4));

    for (int c = 0; c < NCH; c++) {
        const int c1 = c + 1;
        if (c1 < NCH) {                      // prefetch next state burst
            int f = c1*32 + lane;
            bool ok = f < NF;
            #pragma unroll
            for (int j = 0; j < 8; j++)
                sv[j] = ok ? state[(size_t)(s0 + w*8 + j)*NF + f] : 0.f;
        }
        mbar_wait((c&1) ? mbB1 : mbB0, (c>>1)&1);
        {   // MMA: m-tile mt, k-steps kh*4..kh*4+3, 4 n-tiles
            const unsigned a_base = su + (c&1)*ABUF + (16*mt + arow)*ASTRIDE + hi16;
            const unsigned b_base = su + B_OFF + (c&1)*BBUF + arow*80 + hi16;
            #pragma unroll
            for (int kq = 0; kq < 4; kq++) {
                const int kk = kh*4 + kq;
                unsigned a0, a1, a2, a3;
                asm volatile("ldmatrix.sync.aligned.m8n8.x4.shared.b16 "
                             "{%0,%1,%2,%3}, [%4];"
                             : "=r"(a0),"=r"(a1),"=r"(a2),"=r"(a3)
                             : "r"(a_base + 32u*kk));
                unsigned bk = b_base + (unsigned)(kk*16*80);
                unsigned r0,r1,r2,r3,r4,r5,r6,r7;
                asm volatile("ldmatrix.sync.aligned.m8n8.x4.trans.shared.b16 "
                             "{%0,%1,%2,%3}, [%4];"
                             : "=r"(r0),"=r"(r1),"=r"(r2),"=r"(r3) : "r"(bk));
                asm volatile("ldmatrix.sync.aligned.m8n8.x4.trans.shared.b16 "
                             "{%0,%1,%2,%3}, [%4];"
                             : "=r"(r4),"=r"(r5),"=r"(r6),"=r"(r7) : "r"(bk+32u));
                MMA4(acc+0,  r0, r1);
                MMA4(acc+4,  r2, r3);
                MMA4(acc+8,  r4, r5);
                MMA4(acc+12, r6, r7);
            }
        }
        if (c1 < NCH) {                      // consume staged state -> A[(c+1)&1]
            char* Ab = smem + (c1&1)*ABUF;
            int f = c1*32 + lane;
            bool ok = f < NF;
            #pragma unroll
            for (int j = 0; j < 8; j++) {
                uint2 ev = make_uint2(0u, 0u);
                if (ok) {
                    int gidx = f*9 + bucket(sv[j]);
                    ev = *(const uint2*)(smem + E_OFF + gidx*8);
                    linr[j] += *(const float*)(smem + WL_OFF + gidx*4);
                }
                *(uint2*)(Ab + (w*8+j)*ASTRIDE + lane*8) = ev;
            }
        }
        __syncthreads();
        if (tid == 0 && c + 2 < NCH) {       // refill B slot (c&1) with chunk c+2
            unsigned mb = (c&1) ? mbB1 : mbB0;
            mbar_tx(mb, BBUF);
            bulk_g2s(su + B_OFF + (c&1)*BBUF, g_Bw + (size_t)(c+2)*BBUF, BBUF, mb);
        }
    }

    // ---- epilogue: D partials -> smem [2][128][33]; lin warp-reduce ----
    {
        float* dbuf = (float*)smem;
        int r0 = 16*mt + (lane >> 2), cb = 2*(lane & 3);
        #pragma unroll
        for (int nt = 0; nt < 4; nt++) {
            int c0 = 8*nt + cb;
            dbuf[(kh*128 + r0    )*33 + c0    ] = acc[nt*4+0];
            dbuf[(kh*128 + r0    )*33 + c0 + 1] = acc[nt*4+1];
            dbuf[(kh*128 + r0 + 8)*33 + c0    ] = acc[nt*4+2];
            dbuf[(kh*128 + r0 + 8)*33 + c0 + 1] = acc[nt*4+3];
        }
        float* lb = (float*)(smem + LIN_OFF);
        #pragma unroll
        for (int j = 0; j < 8; j++) {
            float v = linr[j];
            #pragma unroll
            for (int o = 16; o; o >>= 1) v += __shfl_xor_sync(0xffffffffu, v, o);
            if (lane == 0) lb[w*8 + j] = v;
        }
    }
    __syncthreads();

    if (tid < 128) {
        const float* d0 = (float*)smem + tid*33;
        const float* d1 = (float*)smem + (128 + tid)*33;
        float am[32];
        #pragma unroll
        for (int j = 0; j < 32; j++) am[j] = prm[1024 + j];          // b2
        for (int k = 0; k < 32; k++) {
            float sc = g1[k] * BN_INV;
            float hk = fmaxf((d0[k] + d1[k])*sc + (b1[k]*sc + be1[k]), 0.f);
            #pragma unroll
            for (int j = 0; j < 32; j++) am[j] += hk * prm[k*32 + j]; // w2
        }
        float x = prm[1152] + prm[1153] + ((float*)(smem + LIN_OFF))[tid];
        #pragma unroll
        for (int j = 0; j < 32; j++) {
            float h2 = fmaxf(am[j]*(prm[1056+j]*BN_INV) + prm[1088+j], 0.f);
            x += h2 * prm[1120 + j];                                  // w3
        }
        out[s0 + tid] = 1.0f / (1.0f + expf(-x));
    }
}

extern "C" void kernel_launch(void* const* d_in, const int* in_sizes, int n_in,
                              void* d_out, int out_size) {
    const float* state = (const float*)d_in[0];
    const float* w_lin = (const float*)d_in[1];
    const float* b_lin = (const float*)d_in[2];
    const float* emb   = (const float*)d_in[3];
    const float* w1    = (const float*)d_in[4];
    const float* b1    = (const float*)d_in[5];
    const float* g1    = (const float*)d_in[6];
    const float* be1   = (const float*)d_in[7];
    const float* w2    = (const float*)d_in[8];
    const float* b2    = (const float*)d_in[9];
    const float* g2    = (const float*)d_in[10];
    const float* be2   = (const float*)d_in[11];
    const float* w3    = (const float*)d_in[12];
    const float* b3    = (const float*)d_in[13];
    float* out = (float*)d_out;

    cudaFuncSetAttribute(fused_mma,
                         cudaFuncAttributeMaxDynamicSharedMemorySize, SMEM_SZ);
    build_e16<<<37, 256>>>(emb);
    build_Bw<<<330, 256>>>(w1);
    fused_mma<<<128, 512, SMEM_SZ>>>(state, w_lin, b1, g1, be1,
                                     w2, b2, g2, be2, w3, b3, b_lin, out);
}

// round 15
// speedup vs baseline: 1.3344x; 1.3344x over previous
#include <cuda_runtime.h>
#include <cuda_fp16.h>
#include <math.h>

#define NF      1044
#define VOCAB   9396
#define NCH     33                  // 33 x 32 fields (K=128 each) = 4224 >= 4176
#define KROW    4224
#define BBUF    (128*80)            // B chunk [128 k][40 halves] = 10240
#define B_OFF   0
#define IDX_OFF (2*BBUF)            // 20480; idxb [2][128 rows][16B]
#define IDXBUF  2048
#define E_OFF   (IDX_OFF+2*IDXBUF)  // 24576; fp16 emb [VOCAB][4] = 75168
#define WL_OFF  (E_OFF+VOCAB*8)     // 99744; fp32 w_lin = 37584
#define PRM_OFF (WL_OFF+VOCAB*4)    // 137328
#define LIN_OFF 141952
#define MBAR_OFF 142464
#define SMEM_SZ  142496
#define BN_INV 0.9999950000374997f

__device__ __align__(16) unsigned char g_e16[VOCAB*8];   // fp16 emb rows
__device__ __align__(16) unsigned char g_Bw[KROW*80];    // fp16 w1 [KROW][40]

__global__ void build_tabs(const float* __restrict__ emb,
                           const float* __restrict__ w1) {
    int t = blockIdx.x*256 + threadIdx.x;
    if (t < VOCAB) {
        __half h[4];
        #pragma unroll
        for (int d = 0; d < 4; d++) h[d] = __float2half_rn(emb[t*4+d]);
        *(uint2*)(g_e16 + t*8) = *(uint2*)h;
    }
    if (t < KROW*20) {
        int np = t % 20, kk = t / 20, n = np*2;
        float v0 = 0.f, v1 = 0.f;
        if (kk < 4176 && n < 32) { v0 = w1[kk*32+n]; v1 = w1[kk*32+n+1]; }
        *(__half2*)(g_Bw + kk*80 + n*2) = __floats2half2_rn(v0, v1);
    }
}

__device__ __forceinline__ void mbar_init(unsigned m, unsigned c) {
    asm volatile("mbarrier.init.shared.b64 [%0], %1;" :: "r"(m), "r"(c) : "memory");
}
__device__ __forceinline__ void mbar_tx(unsigned m, unsigned b) {
    asm volatile("mbarrier.arrive.expect_tx.shared.b64 _, [%0], %1;"
                 :: "r"(m), "r"(b) : "memory");
}
__device__ __forceinline__ void bulk_g2s(unsigned d, const void* s,
                                         unsigned b, unsigned m) {
    asm volatile("cp.async.bulk.shared::cta.global.mbarrier::complete_tx::bytes "
                 "[%0], [%1], %2, [%3];" :: "r"(d), "l"(s), "r"(b), "r"(m) : "memory");
}
__device__ __forceinline__ void mbar_wait(unsigned m, unsigned p) {
    asm volatile(
        "{\n\t.reg .pred P;\nWL%=:\n\t"
        "mbarrier.try_wait.parity.acquire.cta.shared::cta.b64 P, [%0], %1, 0x989680;\n\t"
        "@!P bra WL%=;\n\t}" :: "r"(m), "r"(p) : "memory");
}
__device__ __forceinline__ int bucket(float x) {
    return (x > 5.0f) ? 8 : (int)(x + 2.0f);
}

#define MMA4(C, B0, B1) asm volatile( \
    "mma.sync.aligned.m16n8k16.row.col.f32.f16.f16.f32 " \
    "{%0,%1,%2,%3},{%4,%5,%6,%7},{%8,%9},{%0,%1,%2,%3};" \
    : "+f"((C)[0]), "+f"((C)[1]), "+f"((C)[2]), "+f"((C)[3]) \
    : "r"(a0), "r"(a1), "r"(a2), "r"(a3), "r"(B0), "r"(B1))

__global__ void __launch_bounds__(512, 1)
fused_mma(const float* __restrict__ state, const float* __restrict__ w_lin,
          const float* __restrict__ b1,  const float* __restrict__ g1,
          const float* __restrict__ be1,
          const float* __restrict__ w2,  const float* __restrict__ b2,
          const float* __restrict__ g2,  const float* __restrict__ be2,
          const float* __restrict__ w3,  const float* __restrict__ b3,
          const float* __restrict__ b_lin, float* __restrict__ out) {
    extern __shared__ char smem[];
    const int tid = threadIdx.x, lane = tid & 31, w = tid >> 5;
    const int mt = w >> 1, kh = w & 1;
    const int s0 = blockIdx.x * 128;
    const unsigned su = (unsigned)__cvta_generic_to_shared(smem);
    const unsigned mbE = su+MBAR_OFF, mbB0 = su+MBAR_OFF+8, mbB1 = su+MBAR_OFF+16;
    float* prm = (float*)(smem + PRM_OFF);

    if (tid == 0) { mbar_init(mbE,1); mbar_init(mbB0,1); mbar_init(mbB1,1); }
    __syncthreads();
    if (tid == 0) {
        mbar_tx(mbE, VOCAB*8 + VOCAB*4);
        bulk_g2s(su+E_OFF,  g_e16, VOCAB*8, mbE);
        bulk_g2s(su+WL_OFF, w_lin, VOCAB*4, mbE);
        mbar_tx(mbB0, BBUF); bulk_g2s(su+B_OFF,      g_Bw,      BBUF, mbB0);
        mbar_tx(mbB1, BBUF); bulk_g2s(su+B_OFF+BBUF, g_Bw+BBUF, BBUF, mbB1);
    }
    // staging identity: this lane stages sample row (w*8 + j), field octet o
    const int sj = lane >> 2, so = lane & 3;
    const int srow = w*8 + sj;
    const float* sp = state + (size_t)(s0 + srow)*NF + so*8;
    float lin = 0.f;
    float4 sa, sb;
    sa = *(const float4*)(sp);          // chunk 0, always in-bounds
    sb = *(const float4*)(sp + 4);
    for (int i = tid; i < 1154; i += 512) {
        float v;
        if (i < 1024)      v = w2[i];
        else if (i < 1056) v = b2[i-1024];
        else if (i < 1088) v = g2[i-1056];
        else if (i < 1120) v = be2[i-1088];
        else if (i < 1152) v = w3[i-1120];
        else if (i == 1152) v = b3[0];
        else               v = b_lin[0];
        prm[i] = v;
    }
    mbar_wait(mbE, 0);

    // stage chunk 0 nibbles + lin
    {
        int f0 = so*8;
        int v0=bucket(sa.x),v1=bucket(sa.y),v2=bucket(sa.z),v3=bucket(sa.w);
        int v4=bucket(sb.x),v5=bucket(sb.y),v6=bucket(sb.z),v7=bucket(sb.w);
        unsigned wd = (unsigned)(v0|v1<<4) | (unsigned)(v2|v3<<4)<<8
                    | (unsigned)(v4|v5<<4)<<16 | (unsigned)(v6|v7<<4)<<24;
        *(unsigned*)(smem + IDX_OFF + srow*16 + so*4) = wd;
        const float* wl = (const float*)(smem + WL_OFF);
        lin += wl[(f0+0)*9+v0] + wl[(f0+1)*9+v1] + wl[(f0+2)*9+v2] + wl[(f0+3)*9+v3]
             + wl[(f0+4)*9+v4] + wl[(f0+5)*9+v5] + wl[(f0+6)*9+v6] + wl[(f0+7)*9+v7];
    }
    __syncthreads();

    float acc[16];
    #pragma unroll
    for (int i = 0; i < 16; i++) acc[i] = 0.f;
    const int t3 = lane & 3;
    const int dp4 = (t3 & 1) * 4;              // d-pair byte offset in e-row
    const int tsh = 4 * (t3 >> 1);             // nibble shift from t
    const unsigned nrow = (unsigned)(mt*16 + (lane>>2));

    for (int c = 0; c < NCH; c++) {
        const int c1 = c + 1;
        if (c1 < NCH) {                        // prefetch next chunk's state
            int f0 = c1*32 + so*8;
            sa = (f0 + 4 <= NF) ? *(const float4*)(sp + c1*32)     : make_float4(0,0,0,0);
            sb = (f0 + 8 <= NF) ? *(const float4*)(sp + c1*32 + 4) : make_float4(0,0,0,0);
        }
        mbar_wait((c&1) ? mbB1 : mbB0, (c>>1)&1);
        {   // ---- MMA phase: direct-gather A fragments + B ldmatrix ----
            const char* ib = smem + IDX_OFF + (c&1)*IDXBUF;
            uint2 nw0 = *(const uint2*)(ib + nrow*16 + kh*8);
            uint2 nw1 = *(const uint2*)(ib + (nrow+8)*16 + kh*8);
            const int g1off = (c*32 + kh*16)*9 + (t3>>1)*9;
            const char* E = smem + E_OFF;
            const unsigned b_base = su + B_OFF + (c&1)*BBUF
                                  + (unsigned)((lane&15)*80 + 16*(lane>>4));
            #pragma unroll
            for (int kq = 0; kq < 4; kq++) {
                const unsigned X0 = (kq & 2) ? nw0.y : nw0.x;
                const unsigned X1 = (kq & 2) ? nw1.y : nw1.x;
                const int sh = ((kq & 1) << 4) + tsh;
                int va0 = (X0 >> sh) & 15,      va1 = (X1 >> sh) & 15;
                int va2 = (X0 >> (sh+8)) & 15,  va3 = (X1 >> (sh+8)) & 15;
                int gb = g1off + kq*36;
                unsigned a0 = *(const unsigned*)(E + (gb + va0)*8 + dp4);
                unsigned a1 = *(const unsigned*)(E + (gb + va1)*8 + dp4);
                unsigned a2 = *(const unsigned*)(E + (gb + 18 + va2)*8 + dp4);
                unsigned a3 = *(const unsigned*)(E + (gb + 18 + va3)*8 + dp4);
                const int kk = kh*4 + kq;
                unsigned bk = b_base + (unsigned)(kk*16*80);
                unsigned r0,r1,r2,r3,r4,r5,r6,r7;
                asm volatile("ldmatrix.sync.aligned.m8n8.x4.trans.shared.b16 "
                             "{%0,%1,%2,%3}, [%4];"
                             : "=r"(r0),"=r"(r1),"=r"(r2),"=r"(r3) : "r"(bk));
                asm volatile("ldmatrix.sync.aligned.m8n8.x4.trans.shared.b16 "
                             "{%0,%1,%2,%3}, [%4];"
                             : "=r"(r4),"=r"(r5),"=r"(r6),"=r"(r7) : "r"(bk+32u));
                MMA4(acc+0,  r0, r1);
                MMA4(acc+4,  r2, r3);
                MMA4(acc+8,  r4, r5);
                MMA4(acc+12, r6, r7);
            }
        }
        if (c1 < NCH) {                        // ---- stage chunk c+1 ----
            int f0 = c1*32 + so*8;
            int v0=bucket(sa.x),v1=bucket(sa.y),v2=bucket(sa.z),v3=bucket(sa.w);
            int v4=bucket(sb.x),v5=bucket(sb.y),v6=bucket(sb.z),v7=bucket(sb.w);
            unsigned wd = (unsigned)(v0|v1<<4) | (unsigned)(v2|v3<<4)<<8
                        | (unsigned)(v4|v5<<4)<<16 | (unsigned)(v6|v7<<4)<<24;
            *(unsigned*)(smem + IDX_OFF + (c1&1)*IDXBUF + srow*16 + so*4) = wd;
            const float* wl = (const float*)(smem + WL_OFF);
            if (f0 + 8 <= NF) {
                lin += wl[(f0+0)*9+v0] + wl[(f0+1)*9+v1] + wl[(f0+2)*9+v2]
                     + wl[(f0+3)*9+v3] + wl[(f0+4)*9+v4] + wl[(f0+5)*9+v5]
                     + wl[(f0+6)*9+v6] + wl[(f0+7)*9+v7];
            } else {
                int vv[8] = {v0,v1,v2,v3,v4,v5,v6,v7};
                #pragma unroll
                for (int q = 0; q < 8; q++)
                    if (f0 + q < NF) lin += wl[(f0+q)*9 + vv[q]];
            }
        }
        __syncthreads();
        if (tid == 0 && c + 2 < NCH) {
            unsigned mb = (c&1) ? mbB1 : mbB0;
            mbar_tx(mb, BBUF);
            bulk_g2s(su + B_OFF + (c&1)*BBUF, g_Bw + (size_t)(c+2)*BBUF, BBUF, mb);
        }
    }

    // ---- epilogue: D partials -> smem [2][128][33]; lin 4-lane reduce ----
    {
        float* dbuf = (float*)smem;            // overlays dead B/idx/E-prefix
        int r0 = 16*mt + (lane >> 2), cb = 2*(lane & 3);
        #pragma unroll
        for (int nt = 0; nt < 4; nt++) {
            int c0 = 8*nt + cb;
            dbuf[(kh*128 + r0    )*33 + c0    ] = acc[nt*4+0];
            dbuf[(kh*128 + r0    )*33 + c0 + 1] = acc[nt*4+1];
            dbuf[(kh*128 + r0 + 8)*33 + c0    ] = acc[nt*4+2];
            dbuf[(kh*128 + r0 + 8)*33 + c0 + 1] = acc[nt*4+3];
        }
        float v = lin;
        v += __shfl_xor_sync(0xffffffffu, v, 1);
        v += __shfl_xor_sync(0xffffffffu, v, 2);
        if (so == 0) ((float*)(smem + LIN_OFF))[srow] = v;
    }
    __syncthreads();

    if (tid < 128) {
        const float* d0 = (float*)smem + tid*33;
        const float* d1 = (float*)smem + (128 + tid)*33;
        float am[32];
        #pragma unroll
        for (int j = 0; j < 32; j++) am[j] = prm[1024 + j];           // b2
        for (int k = 0; k < 32; k++) {
            float sc = g1[k] * BN_INV;
            float hk = fmaxf((d0[k] + d1[k])*sc + (b1[k]*sc + be1[k]), 0.f);
            #pragma unroll
            for (int j = 0; j < 32; j++) am[j] += hk * prm[k*32 + j]; // w2
        }
        float x = prm[1152] + prm[1153] + ((float*)(smem + LIN_OFF))[tid];
        #pragma unroll
        for (int j = 0; j < 32; j++) {
            float h2 = fmaxf(am[j]*(prm[1056+j]*BN_INV) + prm[1088+j], 0.f);
            x += h2 * prm[1120 + j];                                   // w3
        }
        out[s0 + tid] = 1.0f / (1.0f + expf(-x));
    }
}

extern "C" void kernel_launch(void* const* d_in, const int* in_sizes, int n_in,
                              void* d_out, int out_size) {
    const float* state = (const float*)d_in[0];
    const float* w_lin = (const float*)d_in[1];
    const float* b_lin = (const float*)d_in[2];
    const float* emb   = (const float*)d_in[3];
    const float* w1    = (const float*)d_in[4];
    const float* b1    = (const float*)d_in[5];
    const float* g1    = (const float*)d_in[6];
    const float* be1   = (const float*)d_in[7];
    const float* w2    = (const float*)d_in[8];
    const float* b2    = (const float*)d_in[9];
    const float* g2    = (const float*)d_in[10];
    const float* be2   = (const float*)d_in[11];
    const float* w3    = (const float*)d_in[12];
    const float* b3    = (const float*)d_in[13];
    float* out = (float*)d_out;

    cudaFuncSetAttribute(fused_mma,
                         cudaFuncAttributeMaxDynamicSharedMemorySize, SMEM_SZ);
    build_tabs<<<330, 256>>>(emb, w1);
    fused_mma<<<128, 512, SMEM_SZ>>>(state, w_lin, b1, g1, be1,
                                     w2, b2, g2, be2, w3, b3, b_lin, out);
}